// round 11
// baseline (speedup 1.0000x reference)
#include <cuda_runtime.h>
#include <cuda_fp16.h>

#define HH 160
#define WW 160
#define DD 96
#define NB 2
#define NC 4
#define BC 8
#define HO 154
#define WO 154
#define DO2 90
#define WIN 7
#define HWP (HH*WW)
#define CH_STRIDE (HH*WW*DD)
#define N_OUT  (BC*HO*WO*DO2)
#define A_FIELD (BC*HWP*DO2)         // 18,432,000
#define PL (DO2/2)                   // 45 half2 per (w) line

#define COV_NORM 1.0208333333333333f
#define CCONST   4.5e-4f
#define INV343   (1.0f/343.0f)

__device__ __half gAh[3*A_FIELD];    // [f][bc][h][w][d'] fp16
__device__ double g_acc;

// ---- pass1: sigmoid of selected channel + D-window for all 4 channels ----
__global__ __launch_bounds__(384) void k_p1(const float* __restrict__ x,
                                            const int* __restrict__ y) {
    __shared__ float svs[4][DD];
    __shared__ int   ys[4][DD];
    int d  = threadIdx.x;
    int ly = threadIdx.y;
    if (blockIdx.x == 0 && d == 0 && ly == 0) g_acc = 0.0;
    int lg = blockIdx.x * 4 + ly;        // line over NB*HWP = 51200
    int b  = lg / HWP;
    int hw = lg - b * HWP;
    int yv = y[lg * DD + d];             // int32 (JAX x64 off)
    const float* xb = x + (b * 4 * HWP + hw) * DD + d;
    float x0 = xb[0];
    float x1 = xb[CH_STRIDE];
    float x2 = xb[2 * CH_STRIDE];
    float x3 = xb[3 * CH_STRIDE];
    float xv = (yv == 0) ? x0 : (yv == 1) ? x1 : (yv == 2) ? x2 : x3;
    svs[ly][d] = __fdividef(1.f, 1.f + __expf(-xv));
    ys[ly][d]  = yv;
    __syncthreads();
    if (d < DO2) {
        float a1[4] = {0,0,0,0}, a2[4] = {0,0,0,0}, a3[4] = {0,0,0,0};
        #pragma unroll
        for (int j = 0; j < WIN; j++) {
            int   yw  = ys[ly][d + j];
            float sv  = svs[ly][d + j];
            float sv2 = sv * sv;
            #pragma unroll
            for (int c = 0; c < 4; c++)
                if (yw == c) { a1[c] += 1.f; a2[c] += sv; a3[c] += sv2; }
        }
        #pragma unroll
        for (int c = 0; c < 4; c++) {
            int base = ((b * 4 + c) * HWP + hw) * DO2 + d;
            gAh[0 * A_FIELD + base] = __float2half(a1[c]);
            gAh[1 * A_FIELD + base] = __float2half(a2[c]);
            gAh[2 * A_FIELD + base] = __float2half(a3[c]);
        }
    }
}

__inline__ __device__ float warpReduceSum(float v) {
    #pragma unroll
    for (int o = 16; o > 0; o >>= 1) v += __shfl_down_sync(0xffffffffu, v, o);
    return v;
}

__inline__ __device__ float svalue(float s1, float s2, float s3) {
    float Sx  = s2 + 0.5f  * (343.f - s1);
    float Sxx = s3 + 0.25f * (343.f - s1);
    float ux = Sx * INV343, uy = s1 * INV343;
    float vx  = COV_NORM * (Sxx * INV343 - ux * ux);
    float vy  = COV_NORM * (s1  * INV343 - uy * uy);
    float vxy = COV_NORM * (s2  * INV343 - ux * uy);
    return __fdividef(vxy + CCONST, vx * vy + CCONST);
}

// W-sum over 7 w at plane h, rounded to half2 (matches old gBh numerics)
__inline__ __device__ void wsum7(const __half2* __restrict__ G0,
                                 const __half2* __restrict__ G1,
                                 const __half2* __restrict__ G2,
                                 int base, __half2& o0, __half2& o1, __half2& o2) {
    float2 a0 = {0,0}, a1 = {0,0}, a2 = {0,0};
    #pragma unroll
    for (int k = 0; k < WIN; k++) {
        float2 v;
        v = __half22float2(G0[base + k * PL]); a0.x += v.x; a0.y += v.y;
        v = __half22float2(G1[base + k * PL]); a1.x += v.x; a1.y += v.y;
        v = __half22float2(G2[base + k * PL]); a2.x += v.x; a2.y += v.y;
    }
    o0 = __floats2half2_rn(a0.x, a0.y);
    o1 = __floats2half2_rn(a1.x, a1.y);
    o2 = __floats2half2_rn(a2.x, a2.y);
}

// ---- fused pass2+3: W-window recomputed from gAh (L1-shared), H-ring in regs ----
// block (48,8): tx = d-pair (45 active), ty = w-offset; grid (20 wtiles, 3 hseg, BC)
__global__ __launch_bounds__(384) void k_p23() {
    int tx = threadIdx.x;
    int ty = threadIdx.y;
    int tid = ty * 48 + tx;
    float acc = 0.f;

    if (tx < PL) {
        int wq = blockIdx.x * 8 + ty;        // output w'
        bool active = (wq < WO);
        if (!active) wq = WO - 1;            // clamp: loads stay in-bounds
        int seg = blockIdx.y;
        int bc  = blockIdx.z;
        int h0  = seg * 52;
        int rem = (seg == 2) ? 0 : 2;        // planes-7 = 49 or 51 = 7*7 + rem

        const __half2* G0 = (const __half2*)(gAh)             + (size_t)bc * HWP * PL;
        const __half2* G1 = (const __half2*)(gAh + A_FIELD)   + (size_t)bc * HWP * PL;
        const __half2* G2 = (const __half2*)(gAh + 2*A_FIELD) + (size_t)bc * HWP * PL;
        int cbase = wq * PL + tx;            // + h*WW*PL per plane

        __half2 r1[7], r2[7], r3[7];
        float2 s1 = {0,0}, s2 = {0,0}, s3 = {0,0};
        float2 local = {0,0};

        // fill group: 7 planes
        #pragma unroll
        for (int k = 0; k < 7; k++) {
            int base = (h0 + k) * (WW * PL) + cbase;
            __half2 a0, a1, a2;
            wsum7(G0, G1, G2, base, a0, a1, a2);
            float2 f;
            f = __half22float2(a0); s1.x += f.x; s1.y += f.y; r1[k] = a0;
            f = __half22float2(a1); s2.x += f.x; s2.y += f.y; r2[k] = a1;
            f = __half22float2(a2); s3.x += f.x; s3.y += f.y; r3[k] = a2;
        }
        local.x += svalue(s1.x, s2.x, s3.x);
        local.y += svalue(s1.y, s2.y, s3.y);

        int h = h0 + 7;
        for (int g = 0; g < 7; g++, h += 7) {       // 7 full groups (always)
            #pragma unroll
            for (int k = 0; k < 7; k++) {
                int base = (h + k) * (WW * PL) + cbase;
                __half2 a0, a1, a2;
                wsum7(G0, G1, G2, base, a0, a1, a2);
                float2 f, o;
                f = __half22float2(a0); o = __half22float2(r1[k]);
                s1.x += f.x - o.x; s1.y += f.y - o.y; r1[k] = a0;
                f = __half22float2(a1); o = __half22float2(r2[k]);
                s2.x += f.x - o.x; s2.y += f.y - o.y; r2[k] = a1;
                f = __half22float2(a2); o = __half22float2(r3[k]);
                s3.x += f.x - o.x; s3.y += f.y - o.y; r3[k] = a2;
                local.x += svalue(s1.x, s2.x, s3.x);
                local.y += svalue(s1.y, s2.y, s3.y);
            }
        }
        #pragma unroll
        for (int k = 0; k < 2; k++) {               // tail (<= 2 planes)
            if (k < rem) {
                int base = (h + k) * (WW * PL) + cbase;
                __half2 a0, a1, a2;
                wsum7(G0, G1, G2, base, a0, a1, a2);
                float2 f, o;
                f = __half22float2(a0); o = __half22float2(r1[k]);
                s1.x += f.x - o.x; s1.y += f.y - o.y; r1[k] = a0;
                f = __half22float2(a1); o = __half22float2(r2[k]);
                s2.x += f.x - o.x; s2.y += f.y - o.y; r2[k] = a1;
                f = __half22float2(a2); o = __half22float2(r3[k]);
                s3.x += f.x - o.x; s3.y += f.y - o.y; r3[k] = a2;
                local.x += svalue(s1.x, s2.x, s3.x);
                local.y += svalue(s1.y, s2.y, s3.y);
            }
        }
        if (active) acc = local.x + local.y;
    }

    __shared__ float red[12];
    float v = warpReduceSum(acc);
    if ((tid & 31) == 0) red[tid >> 5] = v;
    __syncthreads();
    if (tid < 32) {
        v = (tid < 12) ? red[tid] : 0.f;
        v = warpReduceSum(v);
        if (tid == 0) atomicAdd(&g_acc, (double)v);
    }
}

__global__ void k_final(float* out) {
    out[0] = 1.0f - (float)(g_acc * (1.0 / (double)N_OUT));
}

extern "C" void kernel_launch(void* const* d_in, const int* in_sizes, int n_in,
                              void* d_out, int out_size) {
    const float* x = (const float*)d_in[0];
    const int* y = (const int*)d_in[1];
    float* out = (float*)d_out;

    {
        dim3 blk(96, 4);
        k_p1<<<(NB * HWP) / 4, blk>>>(x, y);   // 12800 blocks
    }
    {
        dim3 grid(20, 3, BC);                  // 480 blocks
        dim3 blk(48, 8);                       // 384 threads
        k_p23<<<grid, blk>>>();
    }
    k_final<<<1, 1>>>(out);
}

// round 12
// speedup vs baseline: 1.4321x; 1.4321x over previous
#include <cuda_runtime.h>
#include <cuda_fp16.h>

#define HH 160
#define WW 160
#define DD 96
#define NB 2
#define NC 4
#define BC 8
#define HO 154
#define WO 154
#define DO2 90
#define WIN 7
#define HWP (HH*WW)
#define CH_STRIDE (HH*WW*DD)
#define N_OUT  (BC*HO*WO*DO2)
#define A_FIELD (BC*HWP*DO2)         // 18,432,000
#define B_LINE  (WO*DO2)             // 13860
#define B_FIELD (BC*HH*B_LINE)       // 17,740,800

#define COV_NORM 1.0208333333333333f
#define CCONST   4.5e-4f
#define INV343   (1.0f/343.0f)

__device__ __half gAh[3*A_FIELD];    // [f][bc][h][w][d'] fp16
__device__ __half gBh[3*B_FIELD];    // [f][bc][h][w'][d'] fp16
__device__ double g_acc;

// ---- pass1: sigmoid of selected channel + D-window, packed half2 channels ----
__global__ __launch_bounds__(384) void k_p1(const float* __restrict__ x,
                                            const int* __restrict__ y) {
    __shared__ __half2 s_sv[4][DD];   // half2(sv, sv)
    __shared__ __half2 s_sq[4][DD];   // half2(sv^2, sv^2)
    __shared__ __half2 s_m01[4][DD];  // (y==0, y==1)
    __shared__ __half2 s_m23[4][DD];  // (y==2, y==3)
    int d  = threadIdx.x;
    int ly = threadIdx.y;
    if (blockIdx.x == 0 && d == 0 && ly == 0) g_acc = 0.0;
    int lg = blockIdx.x * 4 + ly;        // line over NB*HWP = 51200
    int b  = lg / HWP;
    int hw = lg - b * HWP;
    int yv = y[lg * DD + d];             // int32 (JAX x64 off)
    const float* xb = x + (b * 4 * HWP + hw) * DD + d;
    float x0 = xb[0];
    float x1 = xb[CH_STRIDE];
    float x2 = xb[2 * CH_STRIDE];
    float x3 = xb[3 * CH_STRIDE];
    float xv = (yv == 0) ? x0 : (yv == 1) ? x1 : (yv == 2) ? x2 : x3;
    float sv = __fdividef(1.f, 1.f + __expf(-xv));
    s_sv[ly][d] = __float2half2_rn(sv);
    s_sq[ly][d] = __float2half2_rn(sv * sv);
    unsigned m01u = (yv == 0) ? 0x00003C00u : (yv == 1) ? 0x3C000000u : 0u;
    unsigned m23u = (yv == 2) ? 0x00003C00u : (yv == 3) ? 0x3C000000u : 0u;
    s_m01[ly][d] = *reinterpret_cast<__half2*>(&m01u);
    s_m23[ly][d] = *reinterpret_cast<__half2*>(&m23u);
    __syncthreads();

    if (d < DO2) {
        __half2 z = __float2half2_rn(0.f);
        __half2 a1_01 = z, a1_23 = z, a2_01 = z, a2_23 = z, a3_01 = z, a3_23 = z;
        #pragma unroll
        for (int j = 0; j < WIN; j++) {
            __half2 m01 = s_m01[ly][d + j];
            __half2 m23 = s_m23[ly][d + j];
            __half2 sh  = s_sv[ly][d + j];
            __half2 qh  = s_sq[ly][d + j];
            a1_01 = __hadd2(a1_01, m01);
            a1_23 = __hadd2(a1_23, m23);
            a2_01 = __hfma2(m01, sh, a2_01);
            a2_23 = __hfma2(m23, sh, a2_23);
            a3_01 = __hfma2(m01, qh, a3_01);
            a3_23 = __hfma2(m23, qh, a3_23);
        }
        const int CS = HWP * DO2;        // channel stride in gAh
        int base = (b * 4 * HWP + hw) * DO2 + d;
        gAh[0*A_FIELD + base         ] = __low2half(a1_01);
        gAh[0*A_FIELD + base +   CS  ] = __high2half(a1_01);
        gAh[0*A_FIELD + base + 2*CS  ] = __low2half(a1_23);
        gAh[0*A_FIELD + base + 3*CS  ] = __high2half(a1_23);
        gAh[1*A_FIELD + base         ] = __low2half(a2_01);
        gAh[1*A_FIELD + base +   CS  ] = __high2half(a2_01);
        gAh[1*A_FIELD + base + 2*CS  ] = __low2half(a2_23);
        gAh[1*A_FIELD + base + 3*CS  ] = __high2half(a2_23);
        gAh[2*A_FIELD + base         ] = __low2half(a3_01);
        gAh[2*A_FIELD + base +   CS  ] = __high2half(a3_01);
        gAh[2*A_FIELD + base + 2*CS  ] = __low2half(a3_23);
        gAh[2*A_FIELD + base + 3*CS  ] = __high2half(a3_23);
    }
}

// ---- pass2: W-window, sliding sum, half2 width (R10, measured best) ----
__global__ __launch_bounds__(192) void k_p2() {
    int tid   = threadIdx.x;
    int chunk = tid / 48;
    int dp    = tid - chunk * 48;        // d-pair index, 0..44 active
    if (dp >= 45) return;
    int h  = blockIdx.x % HH;
    int bc = blockIdx.x / HH;
    int c0 = chunk * 40;
    int wlimit = (c0 + 46 < WW) ? c0 + 46 : WW;

    const __half2* A0 = (const __half2*)(gAh + ((0 * BC + bc) * HWP + h * WW) * DO2) + dp;
    const __half2* A1 = (const __half2*)(gAh + ((1 * BC + bc) * HWP + h * WW) * DO2) + dp;
    const __half2* A2 = (const __half2*)(gAh + ((2 * BC + bc) * HWP + h * WW) * DO2) + dp;
    __half2* B0 = (__half2*)(gBh + ((0 * BC + bc) * HH + h) * B_LINE) + dp;
    __half2* B1 = (__half2*)(gBh + ((1 * BC + bc) * HH + h) * B_LINE) + dp;
    __half2* B2 = (__half2*)(gBh + ((2 * BC + bc) * HH + h) * B_LINE) + dp;
    const int AS = DO2 / 2;
    const int BS = DO2 / 2;

    float2 s1 = {0,0}, s2 = {0,0}, s3 = {0,0};
    for (int w = c0; w < wlimit; w++) {
        float2 v;
        v = __half22float2(A0[w * AS]); s1.x += v.x; s1.y += v.y;
        v = __half22float2(A1[w * AS]); s2.x += v.x; s2.y += v.y;
        v = __half22float2(A2[w * AS]); s3.x += v.x; s3.y += v.y;
        if (w >= c0 + 7) {
            v = __half22float2(A0[(w - 7) * AS]); s1.x -= v.x; s1.y -= v.y;
            v = __half22float2(A1[(w - 7) * AS]); s2.x -= v.x; s2.y -= v.y;
            v = __half22float2(A2[(w - 7) * AS]); s3.x -= v.x; s3.y -= v.y;
        }
        int wp = w - 6;
        if (wp >= c0 && wp < c0 + 40 && wp < WO) {
            B0[wp * BS] = __floats2half2_rn(s1.x, s1.y);
            B1[wp * BS] = __floats2half2_rn(s2.x, s2.y);
            B2[wp * BS] = __floats2half2_rn(s3.x, s3.y);
        }
    }
}

__inline__ __device__ float warpReduceSum(float v) {
    #pragma unroll
    for (int o = 16; o > 0; o >>= 1) v += __shfl_down_sync(0xffffffffu, v, o);
    return v;
}

__inline__ __device__ float svalue(float s1, float s2, float s3) {
    float Sx  = s2 + 0.5f  * (343.f - s1);
    float Sxx = s3 + 0.25f * (343.f - s1);
    float ux = Sx * INV343, uy = s1 * INV343;
    float vx  = COV_NORM * (Sxx * INV343 - ux * ux);
    float vy  = COV_NORM * (s1  * INV343 - uy * uy);
    float vxy = COV_NORM * (s2  * INV343 - ux * uy);
    return __fdividef(vxy + CCONST, vx * vy + CCONST);
}

// ---- pass3: H-window, half2, branch-free steady state, 3 h-segments (R10) ----
__global__ __launch_bounds__(256) void k_p3() {
    int tid = threadIdx.x;
    int j2  = blockIdx.x * 256 + tid;
    int seg = blockIdx.y;
    int bc  = blockIdx.z;
    int h0   = seg * 52;
    int outs = (seg == 2) ? 50 : 52;
    int planes = outs + 6;
    float2 local = {0.f, 0.f};

    if (j2 < B_LINE / 2) {
        const __half2* P0 = (const __half2*)(gBh + (0 * BC + bc) * HH * B_LINE) + j2;
        const __half2* P1 = (const __half2*)(gBh + (1 * BC + bc) * HH * B_LINE) + j2;
        const __half2* P2 = (const __half2*)(gBh + (2 * BC + bc) * HH * B_LINE) + j2;
        const int HS = B_LINE / 2;

        float2 r1[7], r2[7], r3[7];
        float2 s1 = {0,0}, s2 = {0,0}, s3 = {0,0};

        #pragma unroll
        for (int k = 0; k < 7; k++) {
            int h = h0 + k;
            float2 w1 = __half22float2(P0[h * HS]);
            float2 w2 = __half22float2(P1[h * HS]);
            float2 w3 = __half22float2(P2[h * HS]);
            s1.x += w1.x; s1.y += w1.y; r1[k] = w1;
            s2.x += w2.x; s2.y += w2.y; r2[k] = w2;
            s3.x += w3.x; s3.y += w3.y; r3[k] = w3;
        }
        local.x += svalue(s1.x, s2.x, s3.x);
        local.y += svalue(s1.y, s2.y, s3.y);

        int nfull = (planes - 7) / 7;
        int rem   = (planes - 7) % 7;
        int h = h0 + 7;
        for (int g = 0; g < nfull; g++, h += 7) {
            #pragma unroll
            for (int k = 0; k < 7; k++) {
                float2 w1 = __half22float2(P0[(h + k) * HS]);
                float2 w2 = __half22float2(P1[(h + k) * HS]);
                float2 w3 = __half22float2(P2[(h + k) * HS]);
                s1.x += w1.x - r1[k].x; s1.y += w1.y - r1[k].y; r1[k] = w1;
                s2.x += w2.x - r2[k].x; s2.y += w2.y - r2[k].y; r2[k] = w2;
                s3.x += w3.x - r3[k].x; s3.y += w3.y - r3[k].y; r3[k] = w3;
                local.x += svalue(s1.x, s2.x, s3.x);
                local.y += svalue(s1.y, s2.y, s3.y);
            }
        }
        #pragma unroll
        for (int k = 0; k < 6; k++) {
            if (k < rem) {
                float2 w1 = __half22float2(P0[(h + k) * HS]);
                float2 w2 = __half22float2(P1[(h + k) * HS]);
                float2 w3 = __half22float2(P2[(h + k) * HS]);
                s1.x += w1.x - r1[k].x; s1.y += w1.y - r1[k].y; r1[k] = w1;
                s2.x += w2.x - r2[k].x; s2.y += w2.y - r2[k].y; r2[k] = w2;
                s3.x += w3.x - r3[k].x; s3.y += w3.y - r3[k].y; r3[k] = w3;
                local.x += svalue(s1.x, s2.x, s3.x);
                local.y += svalue(s1.y, s2.y, s3.y);
            }
        }
    }

    __shared__ float red[8];
    float v = warpReduceSum(local.x + local.y);
    if ((tid & 31) == 0) red[tid >> 5] = v;
    __syncthreads();
    if (tid < 32) {
        v = (tid < 8) ? red[tid] : 0.f;
        v = warpReduceSum(v);
        if (tid == 0) atomicAdd(&g_acc, (double)v);
    }
}

__global__ void k_final(float* out) {
    out[0] = 1.0f - (float)(g_acc * (1.0 / (double)N_OUT));
}

extern "C" void kernel_launch(void* const* d_in, const int* in_sizes, int n_in,
                              void* d_out, int out_size) {
    const float* x = (const float*)d_in[0];
    const int* y = (const int*)d_in[1];
    float* out = (float*)d_out;

    {
        dim3 blk(96, 4);
        k_p1<<<(NB * HWP) / 4, blk>>>(x, y);        // 12800 blocks
    }
    k_p2<<<BC * HH, 192>>>();                       // 1280 blocks
    {
        dim3 grid((B_LINE / 2 + 255) / 256, 3, BC); // 28 x 3 x 8 = 672 blocks
        k_p3<<<grid, 256>>>();
    }
    k_final<<<1, 1>>>(out);
}

// round 13
// speedup vs baseline: 1.7739x; 1.2386x over previous
#include <cuda_runtime.h>
#include <cuda_fp16.h>

#define HH 160
#define WW 160
#define DD 96
#define NB 2
#define NC 4
#define BC 8
#define HO 154
#define WO 154
#define DO2 90
#define WIN 7
#define HWP (HH*WW)
#define CH_STRIDE (HH*WW*DD)
#define N_OUT  (BC*HO*WO*DO2)
#define PP (NB*2)                 // 4 channel-pair slabs
#define PLANE (WO*DO2)            // 13860 half2 entries per (h) plane

#define COV_NORM 1.0208333333333333f
#define CCONST   4.5e-4f
#define INV343   (1.0f/343.0f)

// [f][b][pr][h][w'][d] as half2 (lanes = channel pair)
__device__ __half2 gB2[3*PP*HH*PLANE];
__device__ double g_acc;

// ---- fused pass1+2: sigmoid + D-window (packed half2) + sliding W-window ----
// block (96,2): 2 lines of (b,h,chunk); grid = NB*HH*4/2 = 640
__global__ __launch_bounds__(192) void k_p12(const float* __restrict__ x,
                                             const int* __restrict__ y) {
    __shared__ __half2 st[2][2][4][DD];     // [buf][line][m01,m23,sv,sq][d]
    __shared__ __half2 ring[2][7][6][DD];   // [line][slot][field][d] (thread-private per d)
    int d  = threadIdx.x;
    int ly = threadIdx.y;
    if (blockIdx.x == 0 && d == 0 && ly == 0) g_acc = 0.0;
    int lg    = blockIdx.x * 2 + ly;        // 0..1279
    int chunk = lg & 3;
    int bh    = lg >> 2;
    int b = bh / HH, h = bh % HH;
    int c0 = chunk * 40;

    const int*   yb  = y + (size_t)(b * HH + h) * WW * DD + d;
    const float* xb0 = x + ((size_t)(b * 4) * HH + h) * WW * DD + d;

    __half2 z = __float2half2_rn(0.f);
    #pragma unroll
    for (int s7 = 0; s7 < 7; s7++)
        #pragma unroll
        for (int f = 0; f < 6; f++)
            ring[ly][s7][f][d] = z;

    float sums[12];
    #pragma unroll
    for (int i = 0; i < 12; i++) sums[i] = 0.f;

    int slot = 0;
    // uniform 46 iterations across both lines (different chunks!) -> syncs never diverge
    for (int it = 0; it < 46; it++) {
        int w  = c0 + it;
        int we = (w < WW) ? w : (WW - 1);   // clamped; out-of-range results never emitted
        int buf = it & 1;
        int yv = yb[we * DD];
        float x0 = xb0[we * DD];
        float x1 = xb0[we * DD + CH_STRIDE];
        float x2 = xb0[we * DD + 2 * CH_STRIDE];
        float x3 = xb0[we * DD + 3 * CH_STRIDE];
        float xv = (yv == 0) ? x0 : (yv == 1) ? x1 : (yv == 2) ? x2 : x3;
        float sv = __fdividef(1.f, 1.f + __expf(-xv));
        unsigned m01u = (yv == 0) ? 0x00003C00u : (yv == 1) ? 0x3C000000u : 0u;
        unsigned m23u = (yv == 2) ? 0x00003C00u : (yv == 3) ? 0x3C000000u : 0u;
        st[buf][ly][0][d] = *reinterpret_cast<__half2*>(&m01u);
        st[buf][ly][1][d] = *reinterpret_cast<__half2*>(&m23u);
        st[buf][ly][2][d] = __float2half2_rn(sv);
        st[buf][ly][3][d] = __float2half2_rn(sv * sv);
        __syncthreads();

        if (d < DO2) {
            __half2 a[6];
            #pragma unroll
            for (int i = 0; i < 6; i++) a[i] = z;
            #pragma unroll
            for (int j = 0; j < WIN; j++) {
                __half2 m01 = st[buf][ly][0][d + j];
                __half2 m23 = st[buf][ly][1][d + j];
                __half2 sh  = st[buf][ly][2][d + j];
                __half2 qh  = st[buf][ly][3][d + j];
                a[0] = __hadd2(a[0], m01);
                a[1] = __hadd2(a[1], m23);
                a[2] = __hfma2(m01, sh, a[2]);
                a[3] = __hfma2(m23, sh, a[3]);
                a[4] = __hfma2(m01, qh, a[4]);
                a[5] = __hfma2(m23, qh, a[5]);
            }
            #pragma unroll
            for (int p = 0; p < 6; p++) {
                float2 nn = __half22float2(a[p]);
                float2 oo = __half22float2(ring[ly][slot][p][d]);
                sums[p * 2]     += nn.x - oo.x;
                sums[p * 2 + 1] += nn.y - oo.y;
                ring[ly][slot][p][d] = a[p];
            }
            int wp = w - 6;
            if (it >= 6 && wp < WO) {
                size_t off = (size_t)h * PLANE + wp * DO2 + d;
                #pragma unroll
                for (int f = 0; f < 3; f++)
                    #pragma unroll
                    for (int pr = 0; pr < 2; pr++) {
                        int p = f * 2 + pr;
                        gB2[((size_t)(f * NB + b) * 2 + pr) * (HH * PLANE) + off] =
                            __floats2half2_rn(sums[p * 2], sums[p * 2 + 1]);
                    }
            }
        }
        slot = (slot == 6) ? 0 : slot + 1;
    }
}

__inline__ __device__ float warpReduceSum(float v) {
    #pragma unroll
    for (int o = 16; o > 0; o >>= 1) v += __shfl_down_sync(0xffffffffu, v, o);
    return v;
}

__inline__ __device__ float svalue(float s1, float s2, float s3) {
    float Sx  = s2 + 0.5f  * (343.f - s1);
    float Sxx = s3 + 0.25f * (343.f - s1);
    float ux = Sx * INV343, uy = s1 * INV343;
    float vx  = COV_NORM * (Sxx * INV343 - ux * ux);
    float vy  = COV_NORM * (s1  * INV343 - uy * uy);
    float vxy = COV_NORM * (s2  * INV343 - ux * uy);
    return __fdividef(vxy + CCONST, vx * vy + CCONST);
}

// ---- pass3: H-window, half2 (lanes = channel pair), 3 h-segments ----
__global__ __launch_bounds__(256) void k_p3() {
    int tid = threadIdx.x;
    int j   = blockIdx.x * 256 + tid;    // over PLANE = 13860
    int seg = blockIdx.y;
    int bp  = blockIdx.z;                // 0..3 = b*2+pr
    int h0   = seg * 52;
    int outs = (seg == 2) ? 50 : 52;
    int planes = outs + 6;
    float2 local = {0.f, 0.f};

    if (j < PLANE) {
        const __half2* P0 = gB2 + (size_t)(0 * PP + bp) * (HH * PLANE) + j;
        const __half2* P1 = gB2 + (size_t)(1 * PP + bp) * (HH * PLANE) + j;
        const __half2* P2 = gB2 + (size_t)(2 * PP + bp) * (HH * PLANE) + j;
        const int HS = PLANE;

        float2 r1[7], r2[7], r3[7];
        float2 s1 = {0,0}, s2 = {0,0}, s3 = {0,0};

        #pragma unroll
        for (int k = 0; k < 7; k++) {
            int h = h0 + k;
            float2 w1 = __half22float2(P0[(size_t)h * HS]);
            float2 w2 = __half22float2(P1[(size_t)h * HS]);
            float2 w3 = __half22float2(P2[(size_t)h * HS]);
            s1.x += w1.x; s1.y += w1.y; r1[k] = w1;
            s2.x += w2.x; s2.y += w2.y; r2[k] = w2;
            s3.x += w3.x; s3.y += w3.y; r3[k] = w3;
        }
        local.x += svalue(s1.x, s2.x, s3.x);
        local.y += svalue(s1.y, s2.y, s3.y);

        int nfull = (planes - 7) / 7;
        int rem   = (planes - 7) % 7;
        int h = h0 + 7;
        for (int g = 0; g < nfull; g++, h += 7) {
            #pragma unroll
            for (int k = 0; k < 7; k++) {
                float2 w1 = __half22float2(P0[(size_t)(h + k) * HS]);
                float2 w2 = __half22float2(P1[(size_t)(h + k) * HS]);
                float2 w3 = __half22float2(P2[(size_t)(h + k) * HS]);
                s1.x += w1.x - r1[k].x; s1.y += w1.y - r1[k].y; r1[k] = w1;
                s2.x += w2.x - r2[k].x; s2.y += w2.y - r2[k].y; r2[k] = w2;
                s3.x += w3.x - r3[k].x; s3.y += w3.y - r3[k].y; r3[k] = w3;
                local.x += svalue(s1.x, s2.x, s3.x);
                local.y += svalue(s1.y, s2.y, s3.y);
            }
        }
        #pragma unroll
        for (int k = 0; k < 6; k++) {
            if (k < rem) {
                float2 w1 = __half22float2(P0[(size_t)(h + k) * HS]);
                float2 w2 = __half22float2(P1[(size_t)(h + k) * HS]);
                float2 w3 = __half22float2(P2[(size_t)(h + k) * HS]);
                s1.x += w1.x - r1[k].x; s1.y += w1.y - r1[k].y; r1[k] = w1;
                s2.x += w2.x - r2[k].x; s2.y += w2.y - r2[k].y; r2[k] = w2;
                s3.x += w3.x - r3[k].x; s3.y += w3.y - r3[k].y; r3[k] = w3;
                local.x += svalue(s1.x, s2.x, s3.x);
                local.y += svalue(s1.y, s2.y, s3.y);
            }
        }
    }

    __shared__ float red[8];
    float v = warpReduceSum(local.x + local.y);
    if ((tid & 31) == 0) red[tid >> 5] = v;
    __syncthreads();
    if (tid < 32) {
        v = (tid < 8) ? red[tid] : 0.f;
        v = warpReduceSum(v);
        if (tid == 0) atomicAdd(&g_acc, (double)v);
    }
}

__global__ void k_final(float* out) {
    out[0] = 1.0f - (float)(g_acc * (1.0 / (double)N_OUT));
}

extern "C" void kernel_launch(void* const* d_in, const int* in_sizes, int n_in,
                              void* d_out, int out_size) {
    const float* x = (const float*)d_in[0];
    const int* y = (const int*)d_in[1];
    float* out = (float*)d_out;

    {
        dim3 blk(96, 2);
        k_p12<<<640, blk>>>(x, y);              // 640 blocks x 192 thr
    }
    {
        dim3 grid((PLANE + 255) / 256, 3, PP);  // 55 x 3 x 4 = 660 blocks
        k_p3<<<grid, 256>>>();
    }
    k_final<<<1, 1>>>(out);
}

// round 14
// speedup vs baseline: 1.8198x; 1.0259x over previous
#include <cuda_runtime.h>
#include <cuda_fp16.h>

#define HH 160
#define WW 160
#define DD 96
#define NB 2
#define NC 4
#define BC 8
#define HO 154
#define WO 154
#define DO2 90
#define WIN 7
#define HWP (HH*WW)
#define CH_STRIDE (HH*WW*DD)
#define N_OUT  (BC*HO*WO*DO2)
#define PP (NB*2)                 // 4 channel-pair slabs
#define PLANE (WO*DO2)            // 13860 half2 entries per (h) plane
#define NCHUNK 8
#define CW 20                     // outputs per chunk
#define CITER (CW+6)              // 26 input planes per chunk

#define COV_NORM 1.0208333333333333f
#define CCONST   4.5e-4f
#define INV343   (1.0f/343.0f)

// [f][b][pr][h][w'][d] as half2 (lanes = channel pair)
__device__ __half2 gB2[3*PP*HH*PLANE];
__device__ double g_acc;

// ---- fused pass1+2: sigmoid + D-window (packed half2) + sliding W-window ----
// block: 96 threads = one (b,h,chunk) line; grid (8, HH, NB) = 2560 blocks
__global__ __launch_bounds__(96) void k_p12(const float* __restrict__ x,
                                            const int* __restrict__ y) {
    __shared__ __half2 st[2][4][DD];     // [buf][m01,m23,sv,sq][d]
    __shared__ __half2 ring[7][6][DD];   // [slot][field][d] (thread-private per d)
    int d = threadIdx.x;
    if (blockIdx.x == 0 && blockIdx.y == 0 && blockIdx.z == 0 && d == 0) g_acc = 0.0;
    int chunk = blockIdx.x;
    int h     = blockIdx.y;
    int b     = blockIdx.z;
    int c0 = chunk * CW;

    const int*   yb  = y + ((size_t)(b * HH + h) * WW) * DD + d;
    const float* xb0 = x + ((size_t)(b * 4 * HH + h) * WW) * DD + d;

    __half2 z = __float2half2_rn(0.f);
    #pragma unroll
    for (int s7 = 0; s7 < 7; s7++)
        #pragma unroll
        for (int f = 0; f < 6; f++)
            ring[s7][f][d] = z;

    float sums[12];
    #pragma unroll
    for (int i = 0; i < 12; i++) sums[i] = 0.f;

    int slot = 0;
    for (int it = 0; it < CITER; it++) {
        int w  = c0 + it;
        int we = (w < WW) ? w : (WW - 1);   // clamp; clamped results never emitted
        int buf = it & 1;
        int yv = yb[we * DD];
        float x0 = xb0[we * DD];
        float x1 = xb0[we * DD + CH_STRIDE];
        float x2 = xb0[we * DD + 2 * CH_STRIDE];
        float x3 = xb0[we * DD + 3 * CH_STRIDE];
        float xv = (yv == 0) ? x0 : (yv == 1) ? x1 : (yv == 2) ? x2 : x3;
        float sv = __fdividef(1.f, 1.f + __expf(-xv));
        unsigned m01u = (yv == 0) ? 0x00003C00u : (yv == 1) ? 0x3C000000u : 0u;
        unsigned m23u = (yv == 2) ? 0x00003C00u : (yv == 3) ? 0x3C000000u : 0u;
        st[buf][0][d] = *reinterpret_cast<__half2*>(&m01u);
        st[buf][1][d] = *reinterpret_cast<__half2*>(&m23u);
        st[buf][2][d] = __float2half2_rn(sv);
        st[buf][3][d] = __float2half2_rn(sv * sv);
        __syncthreads();

        if (d < DO2) {
            __half2 a[6];
            #pragma unroll
            for (int i = 0; i < 6; i++) a[i] = z;
            #pragma unroll
            for (int j = 0; j < WIN; j++) {
                __half2 m01 = st[buf][0][d + j];
                __half2 m23 = st[buf][1][d + j];
                __half2 sh  = st[buf][2][d + j];
                __half2 qh  = st[buf][3][d + j];
                a[0] = __hadd2(a[0], m01);
                a[1] = __hadd2(a[1], m23);
                a[2] = __hfma2(m01, sh, a[2]);
                a[3] = __hfma2(m23, sh, a[3]);
                a[4] = __hfma2(m01, qh, a[4]);
                a[5] = __hfma2(m23, qh, a[5]);
            }
            #pragma unroll
            for (int p = 0; p < 6; p++) {
                float2 nn = __half22float2(a[p]);
                float2 oo = __half22float2(ring[slot][p][d]);
                sums[p * 2]     += nn.x - oo.x;
                sums[p * 2 + 1] += nn.y - oo.y;
                ring[slot][p][d] = a[p];
            }
            int wp = w - 6;
            if (it >= 6 && wp < WO) {
                size_t off = (size_t)h * PLANE + wp * DO2 + d;
                #pragma unroll
                for (int f = 0; f < 3; f++)
                    #pragma unroll
                    for (int pr = 0; pr < 2; pr++) {
                        int p = f * 2 + pr;
                        gB2[((size_t)(f * NB + b) * 2 + pr) * (HH * PLANE) + off] =
                            __floats2half2_rn(sums[p * 2], sums[p * 2 + 1]);
                    }
            }
        }
        slot = (slot == 6) ? 0 : slot + 1;
    }
}

__inline__ __device__ float warpReduceSum(float v) {
    #pragma unroll
    for (int o = 16; o > 0; o >>= 1) v += __shfl_down_sync(0xffffffffu, v, o);
    return v;
}

__inline__ __device__ float svalue(float s1, float s2, float s3) {
    float Sx  = s2 + 0.5f  * (343.f - s1);
    float Sxx = s3 + 0.25f * (343.f - s1);
    float ux = Sx * INV343, uy = s1 * INV343;
    float vx  = COV_NORM * (Sxx * INV343 - ux * ux);
    float vy  = COV_NORM * (s1  * INV343 - uy * uy);
    float vxy = COV_NORM * (s2  * INV343 - ux * uy);
    return __fdividef(vxy + CCONST, vx * vy + CCONST);
}

// ---- pass3: H-window, half2 (lanes = channel pair), 3 h-segments ----
__global__ __launch_bounds__(256) void k_p3() {
    int tid = threadIdx.x;
    int j   = blockIdx.x * 256 + tid;    // over PLANE = 13860
    int seg = blockIdx.y;
    int bp  = blockIdx.z;                // 0..3 = b*2+pr
    int h0   = seg * 52;
    int outs = (seg == 2) ? 50 : 52;
    int planes = outs + 6;
    float2 local = {0.f, 0.f};

    if (j < PLANE) {
        const __half2* P0 = gB2 + (size_t)(0 * PP + bp) * (HH * PLANE) + j;
        const __half2* P1 = gB2 + (size_t)(1 * PP + bp) * (HH * PLANE) + j;
        const __half2* P2 = gB2 + (size_t)(2 * PP + bp) * (HH * PLANE) + j;
        const int HS = PLANE;

        float2 r1[7], r2[7], r3[7];
        float2 s1 = {0,0}, s2 = {0,0}, s3 = {0,0};

        #pragma unroll
        for (int k = 0; k < 7; k++) {
            int h = h0 + k;
            float2 w1 = __half22float2(P0[(size_t)h * HS]);
            float2 w2 = __half22float2(P1[(size_t)h * HS]);
            float2 w3 = __half22float2(P2[(size_t)h * HS]);
            s1.x += w1.x; s1.y += w1.y; r1[k] = w1;
            s2.x += w2.x; s2.y += w2.y; r2[k] = w2;
            s3.x += w3.x; s3.y += w3.y; r3[k] = w3;
        }
        local.x += svalue(s1.x, s2.x, s3.x);
        local.y += svalue(s1.y, s2.y, s3.y);

        int nfull = (planes - 7) / 7;
        int rem   = (planes - 7) % 7;
        int h = h0 + 7;
        for (int g = 0; g < nfull; g++, h += 7) {
            #pragma unroll
            for (int k = 0; k < 7; k++) {
                float2 w1 = __half22float2(P0[(size_t)(h + k) * HS]);
                float2 w2 = __half22float2(P1[(size_t)(h + k) * HS]);
                float2 w3 = __half22float2(P2[(size_t)(h + k) * HS]);
                s1.x += w1.x - r1[k].x; s1.y += w1.y - r1[k].y; r1[k] = w1;
                s2.x += w2.x - r2[k].x; s2.y += w2.y - r2[k].y; r2[k] = w2;
                s3.x += w3.x - r3[k].x; s3.y += w3.y - r3[k].y; r3[k] = w3;
                local.x += svalue(s1.x, s2.x, s3.x);
                local.y += svalue(s1.y, s2.y, s3.y);
            }
        }
        #pragma unroll
        for (int k = 0; k < 6; k++) {
            if (k < rem) {
                float2 w1 = __half22float2(P0[(size_t)(h + k) * HS]);
                float2 w2 = __half22float2(P1[(size_t)(h + k) * HS]);
                float2 w3 = __half22float2(P2[(size_t)(h + k) * HS]);
                s1.x += w1.x - r1[k].x; s1.y += w1.y - r1[k].y; r1[k] = w1;
                s2.x += w2.x - r2[k].x; s2.y += w2.y - r2[k].y; r2[k] = w2;
                s3.x += w3.x - r3[k].x; s3.y += w3.y - r3[k].y; r3[k] = w3;
                local.x += svalue(s1.x, s2.x, s3.x);
                local.y += svalue(s1.y, s2.y, s3.y);
            }
        }
    }

    __shared__ float red[8];
    float v = warpReduceSum(local.x + local.y);
    if ((tid & 31) == 0) red[tid >> 5] = v;
    __syncthreads();
    if (tid < 32) {
        v = (tid < 8) ? red[tid] : 0.f;
        v = warpReduceSum(v);
        if (tid == 0) atomicAdd(&g_acc, (double)v);
    }
}

__global__ void k_final(float* out) {
    out[0] = 1.0f - (float)(g_acc * (1.0 / (double)N_OUT));
}

extern "C" void kernel_launch(void* const* d_in, const int* in_sizes, int n_in,
                              void* d_out, int out_size) {
    const float* x = (const float*)d_in[0];
    const int* y = (const int*)d_in[1];
    float* out = (float*)d_out;

    {
        dim3 grid(NCHUNK, HH, NB);              // 2560 blocks x 96 thr
        k_p12<<<grid, 96>>>(x, y);
    }
    {
        dim3 grid((PLANE + 255) / 256, 3, PP);  // 55 x 3 x 4 = 660 blocks
        k_p3<<<grid, 256>>>();
    }
    k_final<<<1, 1>>>(out);
}